// round 2
// baseline (speedup 1.0000x reference)
#include <cuda_runtime.h>
#include <cstdint>

// Problem constants (from reference setup)
#define B_   32
#define S_   512
#define D_   256
#define KMAX 512          // worst-case token count per row
#define KSM  30           // fast-path cap on tokens kept in shared
#define TT   128          // frames per block tile
#define EPSF 1e-6f
#define INV_SQRT_2PI 0.3989422804014327f

// ---------------- scratch (device globals: no allocation allowed) ----------
__device__ float g_c [B_][KMAX];   // token centers
__device__ float g_is[B_][KMAX];   // 1/sigma
__device__ float g_cf[B_][KMAX];   // 1/(sigma*sqrt(2pi))
__device__ int   g_id[B_][KMAX];   // embed row index
__device__ int   g_K [B_];         // nonzero-dur token count
__device__ int   g_tot[B_];        // total duration (== T for this data)

// dtype-agnostic integer load (inputs may be int32 or int64 depending on jax x64)
__device__ __forceinline__ long long load_i(const void* p, int idx, bool is64) {
    return is64 ? ((const long long*)p)[idx] : (long long)((const int*)p)[idx];
}

// ---------------- kernel A: compact nonzero-duration tokens ---------------
__global__ void prep_kernel(const void* __restrict__ text,
                            const void* __restrict__ durs)
{
    int b = blockIdx.x;
    // dtype detection: text values are all in [1, 256). If stored as int64
    // (little-endian), the second 32-bit word is the high half of text[0] == 0.
    // If int32, it's text[0][1] which is >= 1.
    bool is64 = (((const int*)text)[1] == 0);

    __shared__ int sK;
    if (threadIdx.x == 0) sK = S_;
    __syncthreads();
    // nonzero durs form a prefix; find first zero
    for (int s = threadIdx.x; s < S_; s += blockDim.x) {
        if (load_i(durs, b * S_ + s, is64) == 0) atomicMin(&sK, s);
    }
    __syncthreads();
    int K = sK;

    if (threadIdx.x == 0) {
        long long cum = 0;
        for (int k = 0; k < K; k++) {
            long long d = load_i(durs, b * S_ + k, is64);
            float df  = (float)d;
            float sig = 0.5f * df + EPSF;
            g_c [b][k] = 0.5f * df + (float)cum;   // center = dur/2 + excl cumsum
            g_is[b][k] = 1.0f / sig;
            g_cf[b][k] = INV_SQRT_2PI / sig;       // == exp(-log(sig) - log sqrt(2pi))
            g_id[b][k] = (int)load_i(text, b * S_ + k, is64);
            cum += d;
        }
        g_K  [b] = K;
        g_tot[b] = (int)cum;
    }
}

// ---------------- kernel B: weights + weighted embedding sum ---------------
// shared layout: wsm[KSM*TT] | esm[KSM*D_] | sden[TT]   (46592 B, static)
__global__ __launch_bounds__(256)
void gauss_kernel(const float* __restrict__ embed,
                  float* __restrict__ out, int T)
{
    __shared__ float smem[KSM * TT + KSM * D_ + TT];
    float* wsm  = smem;                 // [s][t] s-major: float4 over t
    float* esm  = smem + KSM * TT;      // [s][d]
    float* sden = esm  + KSM * D_;      // [t] reciprocal denominators

    const int b   = blockIdx.y;
    const int t0  = blockIdx.x * TT;
    const int tid = threadIdx.x;
    if (t0 >= T) return;

    const int K     = g_K[b];
    const int total = g_tot[b];

    if (K <= KSM) {
        // ---- phase 1: gaussian weights for the tile, s-major in shared ----
        const int items = K * TT;
        for (int idx = tid; idx < items; idx += 256) {
            int s = idx >> 7;                 // TT == 128
            int t = idx & (TT - 1);
            float tt = (float)(t0 + t) + 0.5f;
            float z  = (tt - g_c[b][s]) * g_is[b][s];
            wsm[idx] = g_cf[b][s] * __expf(-0.5f * z * z);
        }
        // ---- preload the K embedding rows into shared ----
        for (int idx = tid; idx < K * D_; idx += 256) {
            int s = idx >> 8;                 // D_ == 256
            esm[idx] = embed[g_id[b][s] * D_ + (idx & (D_ - 1))];
        }
        __syncthreads();

        // ---- per-frame reciprocal denominator ----
        if (tid < TT) {
            float den = EPSF;
            for (int s = 0; s < K; s++) den += wsm[s * TT + tid];
            sden[tid] = 1.0f / den;
        }
        __syncthreads();

        // ---- phase 2: each thread owns one d, 4 frames per iter ----
        const int d = tid;
        float* outb = out + ((size_t)b * T + t0) * D_ + d;
        for (int tg = 0; tg < TT; tg += 4) {
            float a0 = 0.f, a1 = 0.f, a2 = 0.f, a3 = 0.f;
            #pragma unroll 4
            for (int s = 0; s < K; s++) {
                float  es = esm[s * D_ + d];                          // broadcast-free, stride-1
                float4 wv = *reinterpret_cast<const float4*>(wsm + s * TT + tg); // broadcast
                a0 = fmaf(wv.x, es, a0);
                a1 = fmaf(wv.y, es, a1);
                a2 = fmaf(wv.z, es, a2);
                a3 = fmaf(wv.w, es, a3);
            }
            int t = t0 + tg;
            if (t + 3 < T) {
                outb[(size_t)(tg + 0) * D_] = (t + 0 < total) ? a0 * sden[tg + 0] : 0.0f;
                outb[(size_t)(tg + 1) * D_] = (t + 1 < total) ? a1 * sden[tg + 1] : 0.0f;
                outb[(size_t)(tg + 2) * D_] = (t + 2 < total) ? a2 * sden[tg + 2] : 0.0f;
                outb[(size_t)(tg + 3) * D_] = (t + 3 < total) ? a3 * sden[tg + 3] : 0.0f;
            } else {
                float av[4] = {a0, a1, a2, a3};
                for (int i = 0; i < 4; i++)
                    if (t + i < T)
                        outb[(size_t)(tg + i) * D_] = (t + i < total) ? av[i] * sden[tg + i] : 0.0f;
            }
        }
    } else {
        // ---- general fallback (K > KSM): per-frame, never hit on this data ----
        float* wf = smem;   // K <= 512 floats fits easily
        const int d = tid;
        for (int t = 0; t < TT; t++) {
            int tabs = t0 + t;
            if (tabs >= T) break;
            for (int s = tid; s < K; s += 256) {
                float tt = (float)tabs + 0.5f;
                float z  = (tt - g_c[b][s]) * g_is[b][s];
                wf[s] = g_cf[b][s] * __expf(-0.5f * z * z);
            }
            __syncthreads();
            float den = EPSF;
            for (int s = 0; s < K; s++) den += wf[s];
            float acc = 0.f;
            for (int s = 0; s < K; s++) acc += wf[s] * embed[g_id[b][s] * D_ + d];
            out[((size_t)b * T + tabs) * D_ + d] = (tabs < total) ? acc / den : 0.0f;
            __syncthreads();
        }
    }
}

// ---------------- launcher ----------------
extern "C" void kernel_launch(void* const* d_in, const int* in_sizes, int n_in,
                              void* d_out, int out_size)
{
    const void*  text  = d_in[0];                 // int32 or int64, detected on-device
    const void*  durs  = d_in[1];
    const float* embed = (const float*)d_in[2];
    float*       out   = (float*)d_out;

    int T = out_size / (B_ * D_);                 // derive T from output size

    prep_kernel<<<B_, 256>>>(text, durs);
    dim3 grid((T + TT - 1) / TT, B_);
    gauss_kernel<<<grid, 256>>>(embed, out, T);
}

// round 3
// speedup vs baseline: 1.3671x; 1.3671x over previous
#include <cuda_runtime.h>
#include <cstdint>

// Problem constants (from reference setup)
#define B_   32
#define S_   512
#define D_   256
#define KSM  30           // fast-path cap on tokens kept in shared
#define TT   128          // frames per block tile
#define EPSF 1e-6f
#define INV_SQRT_2PI 0.3989422804014327f

// shared layout (floats), one contiguous block so the fallback can alias it
#define OFF_W    0                        // [KSM*TT]  weights, s-major
#define OFF_E    (OFF_W  + KSM * TT)      // [KSM*D_]  embedding rows
#define OFF_DEN  (OFF_E  + KSM * D_)      // [TT]      reciprocal denominators
#define OFF_DUR  (OFF_DEN + TT)           // [S_]      durations (float)
#define OFF_C    (OFF_DUR + S_)           // [KSM]
#define OFF_IS   (OFF_C   + KSM)          // [KSM]
#define OFF_CF   (OFF_IS  + KSM)          // [KSM]
#define OFF_ID   (OFF_CF  + KSM)          // [KSM] (ints)
#define SMEM_F   (OFF_ID  + KSM)

// dtype-agnostic integer load (inputs may be int32 or int64 depending on jax x64)
__device__ __forceinline__ long long load_i(const void* p, int idx, bool is64) {
    return is64 ? ((const long long*)p)[idx] : (long long)((const int*)p)[idx];
}

// ---- templated phase-2 inner loop: K embedding values live in registers ----
template<int KC>
__device__ __forceinline__ void phase2(const float* __restrict__ wsm,
                                       const float* __restrict__ esm,
                                       const float* __restrict__ sden,
                                       float* __restrict__ outb,
                                       int t0, int total, int T, int d)
{
    float es[KC];
    #pragma unroll
    for (int s = 0; s < KC; s++) es[s] = esm[s * D_ + d];

    for (int tg = 0; tg < TT; tg += 4) {
        float a0 = 0.f, a1 = 0.f, a2 = 0.f, a3 = 0.f;
        #pragma unroll
        for (int s = 0; s < KC; s++) {
            float4 wv = *reinterpret_cast<const float4*>(wsm + s * TT + tg); // broadcast
            a0 = fmaf(wv.x, es[s], a0);
            a1 = fmaf(wv.y, es[s], a1);
            a2 = fmaf(wv.z, es[s], a2);
            a3 = fmaf(wv.w, es[s], a3);
        }
        int t = t0 + tg;
        if (t + 3 < T) {
            outb[(size_t)(tg + 0) * D_] = (t + 0 < total) ? a0 * sden[tg + 0] : 0.0f;
            outb[(size_t)(tg + 1) * D_] = (t + 1 < total) ? a1 * sden[tg + 1] : 0.0f;
            outb[(size_t)(tg + 2) * D_] = (t + 2 < total) ? a2 * sden[tg + 2] : 0.0f;
            outb[(size_t)(tg + 3) * D_] = (t + 3 < total) ? a3 * sden[tg + 3] : 0.0f;
        } else {
            float av[4] = {a0, a1, a2, a3};
            for (int i = 0; i < 4; i++)
                if (t + i < T)
                    outb[(size_t)(tg + i) * D_] = (t + i < total) ? av[i] * sden[tg + i] : 0.0f;
        }
    }
}

// generic (register-hoist not possible): used for 10 < K <= KSM
__device__ __forceinline__ void phase2_gen(const float* __restrict__ wsm,
                                           const float* __restrict__ esm,
                                           const float* __restrict__ sden,
                                           float* __restrict__ outb,
                                           int t0, int total, int T, int d, int K)
{
    for (int tg = 0; tg < TT; tg += 4) {
        float a0 = 0.f, a1 = 0.f, a2 = 0.f, a3 = 0.f;
        #pragma unroll 4
        for (int s = 0; s < K; s++) {
            float  es = esm[s * D_ + d];
            float4 wv = *reinterpret_cast<const float4*>(wsm + s * TT + tg);
            a0 = fmaf(wv.x, es, a0);
            a1 = fmaf(wv.y, es, a1);
            a2 = fmaf(wv.z, es, a2);
            a3 = fmaf(wv.w, es, a3);
        }
        int t = t0 + tg;
        if (t + 3 < T) {
            outb[(size_t)(tg + 0) * D_] = (t + 0 < total) ? a0 * sden[tg + 0] : 0.0f;
            outb[(size_t)(tg + 1) * D_] = (t + 1 < total) ? a1 * sden[tg + 1] : 0.0f;
            outb[(size_t)(tg + 2) * D_] = (t + 2 < total) ? a2 * sden[tg + 2] : 0.0f;
            outb[(size_t)(tg + 3) * D_] = (t + 3 < total) ? a3 * sden[tg + 3] : 0.0f;
        } else {
            float av[4] = {a0, a1, a2, a3};
            for (int i = 0; i < 4; i++)
                if (t + i < T)
                    outb[(size_t)(tg + i) * D_] = (t + i < total) ? av[i] * sden[tg + i] : 0.0f;
        }
    }
}

// ---------------- single fused kernel ----------------
__global__ __launch_bounds__(256)
void gauss_fused_kernel(const void* __restrict__ text,
                        const void* __restrict__ durs,
                        const float* __restrict__ embed,
                        float* __restrict__ out, int T)
{
    __shared__ float smem[SMEM_F];
    __shared__ int   sK, stot;
    float* wsm  = smem + OFF_W;
    float* esm  = smem + OFF_E;
    float* sden = smem + OFF_DEN;
    float* sdur = smem + OFF_DUR;
    float* s_c  = smem + OFF_C;
    float* s_is = smem + OFF_IS;
    float* s_cf = smem + OFF_CF;
    int*   s_id = (int*)(smem + OFF_ID);

    const int b   = blockIdx.y;
    const int t0  = blockIdx.x * TT;
    const int tid = threadIdx.x;
    if (t0 >= T) return;

    // dtype detection: text values are all in [1,256); if int64 (LE), the
    // second 32-bit word is the high half of text[0] == 0; if int32 it's
    // text[0][1] >= 1.
    const bool is64 = (((const int*)text)[1] == 0);

    // ---- load durations, find K (nonzero durs form a prefix) ----
    if (tid == 0) sK = S_;
    __syncthreads();
    for (int s = tid; s < S_; s += 256) {
        long long dv = load_i(durs, b * S_ + s, is64);
        sdur[s] = (float)dv;
        if (dv == 0) atomicMin(&sK, s);
    }
    __syncthreads();
    const int K = sK;

    if (K <= KSM) {
        // ---- serial param scan over the tiny prefix (from shared) ----
        if (tid == 0) {
            float cum = 0.0f;
            for (int k = 0; k < K; k++) {
                float df  = sdur[k];
                float sig = 0.5f * df + EPSF;
                s_c [k] = 0.5f * df + cum;
                s_is[k] = 1.0f / sig;
                s_cf[k] = INV_SQRT_2PI / sig;
                cum += df;
            }
            stot = (int)cum;
        }
        if (tid < K) s_id[tid] = (int)load_i(text, b * S_ + tid, is64);
        __syncthreads();

        // ---- phase 1: gaussian weights for the tile, s-major in shared ----
        const int items = K * TT;
        for (int idx = tid; idx < items; idx += 256) {
            int s = idx >> 7;                 // TT == 128
            int t = idx & (TT - 1);
            float tt = (float)(t0 + t) + 0.5f;
            float z  = (tt - s_c[s]) * s_is[s];
            wsm[idx] = s_cf[s] * __expf(-0.5f * z * z);
        }
        // ---- preload the K embedding rows into shared ----
        for (int idx = tid; idx < K * D_; idx += 256) {
            int s = idx >> 8;                 // D_ == 256
            esm[idx] = embed[s_id[s] * D_ + (idx & (D_ - 1))];
        }
        __syncthreads();

        // ---- per-frame reciprocal denominator ----
        if (tid < TT) {
            float den = EPSF;
            for (int s = 0; s < K; s++) den += wsm[s * TT + tid];
            sden[tid] = 1.0f / den;
        }
        __syncthreads();

        const int total = stot;
        const int d = tid;
        float* outb = out + ((size_t)b * T + t0) * D_ + d;
        switch (K) {
            case 1:  phase2<1 >(wsm, esm, sden, outb, t0, total, T, d); break;
            case 2:  phase2<2 >(wsm, esm, sden, outb, t0, total, T, d); break;
            case 3:  phase2<3 >(wsm, esm, sden, outb, t0, total, T, d); break;
            case 4:  phase2<4 >(wsm, esm, sden, outb, t0, total, T, d); break;
            case 5:  phase2<5 >(wsm, esm, sden, outb, t0, total, T, d); break;
            case 6:  phase2<6 >(wsm, esm, sden, outb, t0, total, T, d); break;
            case 7:  phase2<7 >(wsm, esm, sden, outb, t0, total, T, d); break;
            case 8:  phase2<8 >(wsm, esm, sden, outb, t0, total, T, d); break;
            case 9:  phase2<9 >(wsm, esm, sden, outb, t0, total, T, d); break;
            case 10: phase2<10>(wsm, esm, sden, outb, t0, total, T, d); break;
            case 0:  phase2<1 >(wsm, esm, sden, outb, t0, 0,     T, d); break; // K==0: all invalid -> zeros
            default: phase2_gen(wsm, esm, sden, outb, t0, total, T, d, K); break;
        }
    } else {
        // ---- general fallback (K > KSM): alias the big shared region ----
        float* fc  = wsm;            // [S_]
        float* fis = wsm + S_;       // [S_]
        float* fcf = wsm + 2 * S_;   // [S_]
        int*   fid = (int*)(wsm + 3 * S_); // [S_]
        float* wf  = wsm + 4 * S_;   // [S_]   (5*S_ = 2560 <= KSM*(TT+D_) = 11520)

        if (tid == 0) {
            float cum = 0.0f;
            for (int k = 0; k < K; k++) {
                float df  = sdur[k];
                float sig = 0.5f * df + EPSF;
                fc [k] = 0.5f * df + cum;
                fis[k] = 1.0f / sig;
                fcf[k] = INV_SQRT_2PI / sig;
                cum += df;
            }
            stot = (int)cum;
        }
        for (int k = tid; k < K; k += 256)
            fid[k] = (int)load_i(text, b * S_ + k, is64);
        __syncthreads();
        const int total = stot;

        const int d = tid;
        for (int t = 0; t < TT; t++) {
            int tabs = t0 + t;
            if (tabs >= T) break;
            for (int s = tid; s < K; s += 256) {
                float tt = (float)tabs + 0.5f;
                float z  = (tt - fc[s]) * fis[s];
                wf[s] = fcf[s] * __expf(-0.5f * z * z);
            }
            __syncthreads();
            float den = EPSF;
            for (int s = 0; s < K; s++) den += wf[s];
            float acc = 0.f;
            for (int s = 0; s < K; s++) acc += wf[s] * embed[fid[s] * D_ + d];
            out[((size_t)b * T + tabs) * D_ + d] = (tabs < total) ? acc / den : 0.0f;
            __syncthreads();
        }
    }
}

// ---------------- launcher: ONE kernel node ----------------
extern "C" void kernel_launch(void* const* d_in, const int* in_sizes, int n_in,
                              void* d_out, int out_size)
{
    const void*  text  = d_in[0];                 // int32 or int64, detected on-device
    const void*  durs  = d_in[1];
    const float* embed = (const float*)d_in[2];
    float*       out   = (float*)d_out;

    int T = out_size / (B_ * D_);                 // derive T from output size

    dim3 grid((T + TT - 1) / TT, B_);
    gauss_fused_kernel<<<grid, 256>>>(text, durs, embed, out, T);
}